// round 15
// baseline (speedup 1.0000x reference)
#include <cuda_runtime.h>
#include <cuda_bf16.h>
#include <cmath>
#include <cstdint>

#define B_  4
#define T_  2048
#define D_  1024
#define H_  16
#define DH_ 64

// ---------------------------------------------------------------------------
// Scratch — identical static set to the passing R11-R13 kernels.
// ---------------------------------------------------------------------------
__device__ __align__(16) float g_q[B_ * H_ * T_ * DH_];      // [B,H,T,dh] fp32
__device__ __align__(16) float g_k[B_ * H_ * T_ * DH_];
__device__ __align__(16) float g_v[B_ * H_ * T_ * DH_];
__device__ __align__(16) float g_attn[B_ * T_ * D_];         // [B,T,D] fp32

// ---------------------------------------------------------------------------
// PTX helpers: ldmatrix / mma.sync only
// ---------------------------------------------------------------------------
struct U4  { uint32_t x, y, z, w; };
struct F4a { float    x, y, z, w; };

__device__ __forceinline__ uint32_t smem_u32(const void* p) {
    uint32_t a;
    asm("{ .reg .u64 t; cvta.to.shared.u64 t, %1; cvt.u32.u64 %0, t; }" : "=r"(a) : "l"(p));
    return a;
}
__device__ __forceinline__ void ldsm4(U4& r, uint32_t addr) {
    asm volatile("ldmatrix.sync.aligned.m8n8.x4.shared.b16 {%0,%1,%2,%3}, [%4];"
                 : "=r"(r.x), "=r"(r.y), "=r"(r.z), "=r"(r.w) : "r"(addr));
}
__device__ __forceinline__ void ldsm4t(U4& r, uint32_t addr) {
    asm volatile("ldmatrix.sync.aligned.m8n8.x4.trans.shared.b16 {%0,%1,%2,%3}, [%4];"
                 : "=r"(r.x), "=r"(r.y), "=r"(r.z), "=r"(r.w) : "r"(addr));
}
__device__ __forceinline__ void mma(F4a& d, const U4& a, uint32_t b0, uint32_t b1) {
    asm volatile(
        "mma.sync.aligned.m16n8k16.row.col.f32.bf16.bf16.f32 "
        "{%0,%1,%2,%3}, {%4,%5,%6,%7}, {%8,%9}, {%0,%1,%2,%3};"
        : "+f"(d.x), "+f"(d.y), "+f"(d.z), "+f"(d.w)
        : "r"(a.x), "r"(a.y), "r"(a.z), "r"(a.w), "r"(b0), "r"(b1));
}

// Convert 8 fp32 (two float4) -> 16B hi chunk + 16B lo chunk (bf16x2 packed)
__device__ __forceinline__ void cvt8(const float4 f0, const float4 f1,
                                     uint4& hi, uint4& lo)
{
    __nv_bfloat16 h0 = __float2bfloat16_rn(f0.x);
    __nv_bfloat16 h1 = __float2bfloat16_rn(f0.y);
    __nv_bfloat16 h2 = __float2bfloat16_rn(f0.z);
    __nv_bfloat16 h3 = __float2bfloat16_rn(f0.w);
    __nv_bfloat16 h4 = __float2bfloat16_rn(f1.x);
    __nv_bfloat16 h5 = __float2bfloat16_rn(f1.y);
    __nv_bfloat16 h6 = __float2bfloat16_rn(f1.z);
    __nv_bfloat16 h7 = __float2bfloat16_rn(f1.w);
    __nv_bfloat16 l0 = __float2bfloat16_rn(f0.x - __bfloat162float(h0));
    __nv_bfloat16 l1 = __float2bfloat16_rn(f0.y - __bfloat162float(h1));
    __nv_bfloat16 l2 = __float2bfloat16_rn(f0.z - __bfloat162float(h2));
    __nv_bfloat16 l3 = __float2bfloat16_rn(f0.w - __bfloat162float(h3));
    __nv_bfloat16 l4 = __float2bfloat16_rn(f1.x - __bfloat162float(h4));
    __nv_bfloat16 l5 = __float2bfloat16_rn(f1.y - __bfloat162float(h5));
    __nv_bfloat16 l6 = __float2bfloat16_rn(f1.z - __bfloat162float(h6));
    __nv_bfloat16 l7 = __float2bfloat16_rn(f1.w - __bfloat162float(h7));
    __nv_bfloat162 p;
    p = __nv_bfloat162(h0, h1); hi.x = *(uint32_t*)&p;
    p = __nv_bfloat162(h2, h3); hi.y = *(uint32_t*)&p;
    p = __nv_bfloat162(h4, h5); hi.z = *(uint32_t*)&p;
    p = __nv_bfloat162(h6, h7); hi.w = *(uint32_t*)&p;
    p = __nv_bfloat162(l0, l1); lo.x = *(uint32_t*)&p;
    p = __nv_bfloat162(l2, l3); lo.y = *(uint32_t*)&p;
    p = __nv_bfloat162(l4, l5); lo.z = *(uint32_t*)&p;
    p = __nv_bfloat162(l6, l7); lo.w = *(uint32_t*)&p;
}

#define MMA3(Dst, b0h, b1h, b0l, b1l)  \
    mma(Dst, aH, b0h, b1h);            \
    mma(Dst, aH, b0l, b1l);            \
    mma(Dst, aL, b0h, b1h);

// ---------------------------------------------------------------------------
// Fused convert+mma GEMM — verbatim from passing R13 (64x128 tiles).
// ---------------------------------------------------------------------------
#define GK   1024
#define BK   64
#define NKB  (GK / BK)   // 16
#define G_AH 0
#define G_AL 8192
#define G_BH 16384
#define G_BL 32768
#define GEMM_SMEM 49152

#define EPI(C, MT, NT) do {                                                        \
    const int r_lo = row0 + wm * 32 + (MT) * 16 + (lane >> 2);                     \
    const int r_hi = r_lo + 8;                                                     \
    const int col  = col0 + wn * 32 + (NT) * 8 + 2 * (lane & 3);                   \
    const float b0 = bias[col], b1 = bias[col + 1];                                \
    float2 vlo = make_float2((C).x + b0, (C).y + b1);                              \
    float2 vhi = make_float2((C).z + b0, (C).w + b1);                              \
    if (MODE == 0) {                                                               \
        *(float2*)(out + (size_t)r_lo * 1024 + col) = vlo;                         \
        *(float2*)(out + (size_t)r_hi * 1024 + col) = vhi;                         \
    } else {                                                                       \
        const int sec  = col >> 10;                                               \
        const int cc   = col & 1023;                                              \
        const int head = cc >> 6;                                                 \
        const int dd   = cc & 63;                                                 \
        float* buf = (sec == 0) ? g_q : (sec == 1) ? g_k : g_v;                    \
        { const int bb = r_lo >> 11, t = r_lo & 2047;                              \
          *(float2*)(buf + ((size_t)(bb * H_ + head) * T_ + t) * DH_ + dd) = vlo; }\
        { const int bb = r_hi >> 11, t = r_hi & 2047;                              \
          *(float2*)(buf + ((size_t)(bb * H_ + head) * T_ + t) * DH_ + dd) = vhi; }\
    }                                                                              \
} while (0)

template <int MODE>
__global__ __launch_bounds__(256) void gemm_fused_kernel(
    const float* __restrict__ Ain,
    const float* __restrict__ W,
    const float* __restrict__ bias, float* __restrict__ out)
{
    const int Ntot = (MODE == 1) ? 3072 : 1024;
    extern __shared__ char smem[];
    const uint32_t sb = smem_u32(smem);

    const int tid  = threadIdx.x;
    const int lane = tid & 31;
    const int wid  = tid >> 5;
    const int wm   = wid & 1;
    const int wn   = wid >> 1;

    const int col0 = blockIdx.x * 128;
    const int row0 = blockIdx.y * 64;

    const float* A = (MODE == 0) ? (const float*)g_attn : Ain;

    const int cpR = tid >> 2;
    const int cpC = (tid & 3) * 16;
    const int cpU = (tid & 3) * 2;

    F4a c00 = {0,0,0,0}, c01 = {0,0,0,0}, c02 = {0,0,0,0}, c03 = {0,0,0,0};
    F4a c10 = {0,0,0,0}, c11 = {0,0,0,0}, c12 = {0,0,0,0}, c13 = {0,0,0,0};

    const int a_r  = wm * 32 + (lane & 15);
    const int a_s7 = a_r & 7;
    const int b_rl = lane & 15;
    const int b_c0 = wn * 4 + (lane >> 4);
    const int b_c1 = b_c0 + 2;
    const int b_h0 = (b_c0 >> 3) << 7;
    const int b_u0 = b_c0 & 7;
    const int b_h1 = (b_c1 >> 3) << 7;
    const int b_u1 = b_c1 & 7;

#pragma unroll 1
    for (int kb = 0; kb < NKB; kb++) {
        const int kbase = kb * BK;

        __syncthreads();

        {
            const float* src = A + (size_t)(row0 + cpR) * GK + kbase + cpC;
            float4 f0 = *(const float4*)(src + 0);
            float4 f1 = *(const float4*)(src + 4);
            float4 f2 = *(const float4*)(src + 8);
            float4 f3 = *(const float4*)(src + 12);
            uint4 hi, lo;
            cvt8(f0, f1, hi, lo);
            uint32_t off = cpR * 128 + (((cpU + 0) ^ (cpR & 7)) << 4);
            *(uint4*)(smem + G_AH + off) = hi;
            *(uint4*)(smem + G_AL + off) = lo;
            cvt8(f2, f3, hi, lo);
            off = cpR * 128 + (((cpU + 1) ^ (cpR & 7)) << 4);
            *(uint4*)(smem + G_AH + off) = hi;
            *(uint4*)(smem + G_AL + off) = lo;
        }
        {
            const float* src = W + (size_t)(kbase + cpR) * Ntot + col0 + cpC;
            float4 f0 = *(const float4*)(src + 0);
            float4 f1 = *(const float4*)(src + 4);
            float4 f2 = *(const float4*)(src + 8);
            float4 f3 = *(const float4*)(src + 12);
            uint4 hi, lo;
            cvt8(f0, f1, hi, lo);
            uint32_t off = cpR * 256 + (((cpU + 0) ^ (cpR & 7)) << 4);
            *(uint4*)(smem + G_BH + off) = hi;
            *(uint4*)(smem + G_BL + off) = lo;
            cvt8(f2, f3, hi, lo);
            off = cpR * 256 + (((cpU + 1) ^ (cpR & 7)) << 4);
            *(uint4*)(smem + G_BH + off) = hi;
            *(uint4*)(smem + G_BL + off) = lo;
        }
        {
            const float* src = W + (size_t)(kbase + cpR) * Ntot + col0 + 64 + cpC;
            float4 f0 = *(const float4*)(src + 0);
            float4 f1 = *(const float4*)(src + 4);
            float4 f2 = *(const float4*)(src + 8);
            float4 f3 = *(const float4*)(src + 12);
            uint4 hi, lo;
            cvt8(f0, f1, hi, lo);
            uint32_t off = cpR * 256 + 128 + (((cpU + 0) ^ (cpR & 7)) << 4);
            *(uint4*)(smem + G_BH + off) = hi;
            *(uint4*)(smem + G_BL + off) = lo;
            cvt8(f2, f3, hi, lo);
            off = cpR * 256 + 128 + (((cpU + 1) ^ (cpR & 7)) << 4);
            *(uint4*)(smem + G_BH + off) = hi;
            *(uint4*)(smem + G_BL + off) = lo;
        }

        __syncthreads();

#pragma unroll 1
        for (int ks = 0; ks < 4; ks++) {
            const int br = ks * 16 + b_rl;
            const uint32_t boff0 = br * 256 + b_h0 + ((b_u0 ^ (br & 7)) << 4);
            const uint32_t boff1 = br * 256 + b_h1 + ((b_u1 ^ (br & 7)) << 4);
            U4 bH0, bL0, bH1, bL1;
            ldsm4t(bH0, sb + G_BH + boff0);
            ldsm4t(bL0, sb + G_BL + boff0);
            ldsm4t(bH1, sb + G_BH + boff1);
            ldsm4t(bL1, sb + G_BL + boff1);

            const uint32_t asw = (uint32_t)(((2 * ks + (lane >> 4)) ^ a_s7) << 4);
            U4 aH, aL;
            ldsm4(aH, sb + G_AH + a_r * 128 + asw);
            ldsm4(aL, sb + G_AL + a_r * 128 + asw);
            MMA3(c00, bH0.x, bH0.y, bL0.x, bL0.y)
            MMA3(c01, bH0.z, bH0.w, bL0.z, bL0.w)
            MMA3(c02, bH1.x, bH1.y, bL1.x, bL1.y)
            MMA3(c03, bH1.z, bH1.w, bL1.z, bL1.w)
            ldsm4(aH, sb + G_AH + (a_r + 16) * 128 + asw);
            ldsm4(aL, sb + G_AL + (a_r + 16) * 128 + asw);
            MMA3(c10, bH0.x, bH0.y, bL0.x, bL0.y)
            MMA3(c11, bH0.z, bH0.w, bL0.z, bL0.w)
            MMA3(c12, bH1.x, bH1.y, bL1.x, bL1.y)
            MMA3(c13, bH1.z, bH1.w, bL1.z, bL1.w)
        }
    }

    EPI(c00, 0, 0); EPI(c01, 0, 1); EPI(c02, 0, 2); EPI(c03, 0, 3);
    EPI(c10, 1, 0); EPI(c11, 1, 1); EPI(c12, 1, 2); EPI(c13, 1, 3);
}

// ---------------------------------------------------------------------------
// RoPE on q and k in place (fp32) — verbatim.
// ---------------------------------------------------------------------------
struct RopeInv { float v[32]; };

__global__ __launch_bounds__(256) void rope_kernel(RopeInv tab) {
    const int idx = blockIdx.x * blockDim.x + threadIdx.x;
    const int d   = idx & 31;
    const int row = idx >> 5;
    const int t   = row & (T_ - 1);

    const float ang = (float)t * tab.v[d];
    float s, c;
    sincosf(ang, &s, &c);

    const size_t base = (size_t)row * DH_;
    {
        float x1 = g_q[base + d], x2 = g_q[base + d + 32];
        g_q[base + d]      = x1 * c - x2 * s;
        g_q[base + d + 32] = x1 * s + x2 * c;
    }
    {
        float x1 = g_k[base + d], x2 = g_k[base + d + 32];
        g_k[base + d]      = x1 * c - x2 * s;
        g_k[base + d + 32] = x1 * s + x2 * c;
    }
}

// ---------------------------------------------------------------------------
// Tensor-core flash attention, WIDE Q-tile: 128 queries/CTA, 64-key tiles.
//   8 warps 2(M: 64 rows)x4(N: 16). Warp S-tile 64x16, O-tile 64x16.
//   S acc 32 + O acc 32 regs. Same proven fragment paths as R12/R13.
// ---------------------------------------------------------------------------
#define A_QH 0
#define A_QL 16384
#define A_KH 32768
#define A_KL 40960
#define A_VH 49152
#define A_VL 57344
#define A_PH 65536
#define A_PL 81920
#define A_PS 98304
#define A_MS 133120
#define A_LS 133632
#define A_CS 134144
#define ATTN_SMEM 134656

#define S_MT(S0, S1, AR)                            \
    ldsm4(aH, sb + A_QH + (AR) * 128 + asw);        \
    ldsm4(aL, sb + A_QL + (AR) * 128 + asw);        \
    MMA3(S0, bH.x, bH.y, bL.x, bL.y)                \
    MMA3(S1, bH.z, bH.w, bL.z, bL.w)

#define P_MT(O0, O1, AR)                            \
    ldsm4(aH, sb + A_PH + (AR) * 128 + asw);        \
    ldsm4(aL, sb + A_PL + (AR) * 128 + asw);        \
    MMA3(O0, bH.x, bH.y, bL.x, bL.y)                \
    MMA3(O1, bH.z, bH.w, bL.z, bL.w)

#define S_ST(S0, S1, MT) {                                                  \
    const int r = wm * 64 + (MT) * 16 + (lane >> 2);                        \
    const int cB = wn * 16 + 2 * (lane & 3);                                \
    *(float2*)(Ps + (r + 0) * 68 + cB)     = make_float2((S0).x, (S0).y);   \
    *(float2*)(Ps + (r + 8) * 68 + cB)     = make_float2((S0).z, (S0).w);   \
    *(float2*)(Ps + (r + 0) * 68 + cB + 8) = make_float2((S1).x, (S1).y);   \
    *(float2*)(Ps + (r + 8) * 68 + cB + 8) = make_float2((S1).z, (S1).w);   \
}

#define O_RESC(O0, O1, MT) {                                                \
    const int r = wm * 64 + (MT) * 16 + (lane >> 2);                        \
    const float cl = cs[r], ch = cs[r + 8];                                 \
    (O0).x *= cl; (O0).y *= cl; (O0).z *= ch; (O0).w *= ch;                 \
    (O1).x *= cl; (O1).y *= cl; (O1).z *= ch; (O1).w *= ch;                 \
}

#define O_WR(O0, O1, MT) {                                                  \
    const int r = wm * 64 + (MT) * 16 + (lane >> 2);                        \
    const float il = 1.0f / ls[r], ih = 1.0f / ls[r + 8];                   \
    *(float2*)(obase + (size_t)(r + 0) * D_ + dcB)                          \
        = make_float2((O0).x * il, (O0).y * il);                            \
    *(float2*)(obase + (size_t)(r + 8) * D_ + dcB)                          \
        = make_float2((O0).z * ih, (O0).w * ih);                            \
    *(float2*)(obase + (size_t)(r + 0) * D_ + dcB + 8)                      \
        = make_float2((O1).x * il, (O1).y * il);                            \
    *(float2*)(obase + (size_t)(r + 8) * D_ + dcB + 8)                      \
        = make_float2((O1).z * ih, (O1).w * ih);                            \
}

__global__ __launch_bounds__(256) void attn_mma_kernel() {
    extern __shared__ char sm8[];
    const uint32_t sb = smem_u32(sm8);
    float* Ps = (float*)(sm8 + A_PS);     // [128][68]
    float* ms = (float*)(sm8 + A_MS);
    float* ls = (float*)(sm8 + A_LS);
    float* cs = (float*)(sm8 + A_CS);

    const int tid  = threadIdx.x;
    const int lane = tid & 31;
    const int wid  = tid >> 5;
    const int wm   = wid & 1;       // M: 64 rows each
    const int wn   = wid >> 1;      // N: 16 each

    const int bh = blockIdx.y;
    const int qb = blockIdx.x;      // 0..15 (128 queries each)

    const float* Qg = g_q + (size_t)bh * (T_ * DH_) + (size_t)qb * (128 * DH_);
    const float* Kg = g_k + (size_t)bh * (T_ * DH_);
    const float* Vg = g_v + (size_t)bh * (T_ * DH_);

    // K/V copy mapping (64 rows): 4 threads/row, 16 fp32 each
    const int cpR = tid >> 2;
    const int cpC = (tid & 3) * 16;
    const int cpU = (tid & 3) * 2;
    // Q copy mapping (128 rows): 2 threads/row, 32 fp32 each
    const int qR = tid >> 1;
    const int qC = (tid & 1) * 32;
    const int qU = (tid & 1) * 4;

    // ---- load Q (pre-scaled by 1/8), convert to hi/lo ----
    {
        const float* src = Qg + (size_t)qR * DH_ + qC;
#pragma unroll
        for (int j = 0; j < 2; j++) {
            float4 f0 = *(const float4*)(src + j * 16 + 0);
            float4 f1 = *(const float4*)(src + j * 16 + 4);
            float4 f2 = *(const float4*)(src + j * 16 + 8);
            float4 f3 = *(const float4*)(src + j * 16 + 12);
            f0.x *= 0.125f; f0.y *= 0.125f; f0.z *= 0.125f; f0.w *= 0.125f;
            f1.x *= 0.125f; f1.y *= 0.125f; f1.z *= 0.125f; f1.w *= 0.125f;
            f2.x *= 0.125f; f2.y *= 0.125f; f2.z *= 0.125f; f2.w *= 0.125f;
            f3.x *= 0.125f; f3.y *= 0.125f; f3.z *= 0.125f; f3.w *= 0.125f;
            uint4 hi, lo;
            cvt8(f0, f1, hi, lo);
            uint32_t off = qR * 128 + (((qU + j * 2 + 0) ^ (qR & 7)) << 4);
            *(uint4*)(sm8 + A_QH + off) = hi;
            *(uint4*)(sm8 + A_QL + off) = lo;
            cvt8(f2, f3, hi, lo);
            off = qR * 128 + (((qU + j * 2 + 1) ^ (qR & 7)) << 4);
            *(uint4*)(sm8 + A_QH + off) = hi;
            *(uint4*)(sm8 + A_QL + off) = lo;
        }
    }
    if (tid < 128) { ms[tid] = -1e30f; ls[tid] = 0.0f; }

    F4a oA0 = {0,0,0,0}, oA1 = {0,0,0,0}, oB0 = {0,0,0,0}, oB1 = {0,0,0,0};
    F4a oC0 = {0,0,0,0}, oC1 = {0,0,0,0}, oD0 = {0,0,0,0}, oD1 = {0,0,0,0};

    const int a_r  = wm * 64 + (lane & 15);   // + mt*16
    const int a_s7 = a_r & 7;
    const int k_r  = wn * 16 + ((lane >> 4) << 3) + (lane & 7);
    const int k_c  = (lane >> 3) & 1;
    const int v_rl = lane & 15;
    const int v_ch = wn * 2 + (lane >> 4);

#pragma unroll 1
    for (int kt = 0; kt < 32; kt++) {
        __syncthreads();

        // ---- copy K, V tiles ----
        {
            const float* src = Kg + (size_t)(kt * 64 + cpR) * DH_ + cpC;
            float4 f0 = *(const float4*)(src + 0);
            float4 f1 = *(const float4*)(src + 4);
            float4 f2 = *(const float4*)(src + 8);
            float4 f3 = *(const float4*)(src + 12);
            uint4 hi, lo;
            cvt8(f0, f1, hi, lo);
            uint32_t off = cpR * 128 + (((cpU + 0) ^ (cpR & 7)) << 4);
            *(uint4*)(sm8 + A_KH + off) = hi;
            *(uint4*)(sm8 + A_KL + off) = lo;
            cvt8(f2, f3, hi, lo);
            off = cpR * 128 + (((cpU + 1) ^ (cpR & 7)) << 4);
            *(uint4*)(sm8 + A_KH + off) = hi;
            *(uint4*)(sm8 + A_KL + off) = lo;
        }
        {
            const float* src = Vg + (size_t)(kt * 64 + cpR) * DH_ + cpC;
            float4 f0 = *(const float4*)(src + 0);
            float4 f1 = *(const float4*)(src + 4);
            float4 f2 = *(const float4*)(src + 8);
            float4 f3 = *(const float4*)(src + 12);
            uint4 hi, lo;
            cvt8(f0, f1, hi, lo);
            uint32_t off = cpR * 128 + (((cpU + 0) ^ (cpR & 7)) << 4);
            *(uint4*)(sm8 + A_VH + off) = hi;
            *(uint4*)(sm8 + A_VL + off) = lo;
            cvt8(f2, f3, hi, lo);
            off = cpR * 128 + (((cpU + 1) ^ (cpR & 7)) << 4);
            *(uint4*)(sm8 + A_VH + off) = hi;
            *(uint4*)(sm8 + A_VL + off) = lo;
        }
        __syncthreads();

        // ---- S = Q @ K^T (warp tile 64x16) ----
        {
            F4a sA0 = {0,0,0,0}, sA1 = {0,0,0,0}, sB0 = {0,0,0,0}, sB1 = {0,0,0,0};
            F4a sC0 = {0,0,0,0}, sC1 = {0,0,0,0}, sD0 = {0,0,0,0}, sD1 = {0,0,0,0};
#pragma unroll 1
            for (int ks = 0; ks < 4; ks++) {
                const uint32_t koff = k_r * 128 + (((2 * ks + k_c) ^ (k_r & 7)) << 4);
                U4 bH, bL;
                ldsm4(bH, sb + A_KH + koff);
                ldsm4(bL, sb + A_KL + koff);
                const uint32_t asw = (uint32_t)(((2 * ks + (lane >> 4)) ^ a_s7) << 4);
                U4 aH, aL;
                S_MT(sA0, sA1, a_r +  0)
                S_MT(sB0, sB1, a_r + 16)
                S_MT(sC0, sC1, a_r + 32)
                S_MT(sD0, sD1, a_r + 48)
            }
            S_ST(sA0, sA1, 0)
            S_ST(sB0, sB1, 1)
            S_ST(sC0, sC1, 2)
            S_ST(sD0, sD1, 3)
        }
        __syncthreads();

        // ---- online softmax (2 threads per row, 32 cols each) ----
        {
            const int row = tid >> 1;
            const int q   = tid & 1;
            const float* pr = Ps + row * 68 + q * 32;
            float4 p0 = *(const float4*)(pr + 0);
            float4 p1 = *(const float4*)(pr + 4);
            float4 p2 = *(const float4*)(pr + 8);
            float4 p3 = *(const float4*)(pr + 12);
            float4 p4 = *(const float4*)(pr + 16);
            float4 p5 = *(const float4*)(pr + 20);
            float4 p6 = *(const float4*)(pr + 24);
            float4 p7 = *(const float4*)(pr + 28);
            float mx = fmaxf(fmaxf(fmaxf(p0.x, p0.y), fmaxf(p0.z, p0.w)),
                             fmaxf(fmaxf(p1.x, p1.y), fmaxf(p1.z, p1.w)));
            mx = fmaxf(mx, fmaxf(fmaxf(fmaxf(p2.x, p2.y), fmaxf(p2.z, p2.w)),
                                 fmaxf(fmaxf(p3.x, p3.y), fmaxf(p3.z, p3.w))));
            mx = fmaxf(mx, fmaxf(fmaxf(fmaxf(p4.x, p4.y), fmaxf(p4.z, p4.w)),
                                 fmaxf(fmaxf(p5.x, p5.y), fmaxf(p5.z, p5.w))));
            mx = fmaxf(mx, fmaxf(fmaxf(fmaxf(p6.x, p6.y), fmaxf(p6.z, p6.w)),
                                 fmaxf(fmaxf(p7.x, p7.y), fmaxf(p7.z, p7.w))));
            mx = fmaxf(mx, __shfl_xor_sync(0xffffffffu, mx, 1));
            const float m_old = ms[row];
            const float m_new = fmaxf(m_old, mx);
            p0.x = __expf(p0.x - m_new); p0.y = __expf(p0.y - m_new);
            p0.z = __expf(p0.z - m_new); p0.w = __expf(p0.w - m_new);
            p1.x = __expf(p1.x - m_new); p1.y = __expf(p1.y - m_new);
            p1.z = __expf(p1.z - m_new); p1.w = __expf(p1.w - m_new);
            p2.x = __expf(p2.x - m_new); p2.y = __expf(p2.y - m_new);
            p2.z = __expf(p2.z - m_new); p2.w = __expf(p2.w - m_new);
            p3.x = __expf(p3.x - m_new); p3.y = __expf(p3.y - m_new);
            p3.z = __expf(p3.z - m_new); p3.w = __expf(p3.w - m_new);
            p4.x = __expf(p4.x - m_new); p4.y = __expf(p4.y - m_new);
            p4.z = __expf(p4.z - m_new); p4.w = __expf(p4.w - m_new);
            p5.x = __expf(p5.x - m_new); p5.y = __expf(p5.y - m_new);
            p5.z = __expf(p5.z - m_new); p5.w = __expf(p5.w - m_new);
            p6.x = __expf(p6.x - m_new); p6.y = __expf(p6.y - m_new);
            p6.z = __expf(p6.z - m_new); p6.w = __expf(p6.w - m_new);
            p7.x = __expf(p7.x - m_new); p7.y = __expf(p7.y - m_new);
            p7.z = __expf(p7.z - m_new); p7.w = __expf(p7.w - m_new);
            float sum = p0.x + p0.y + p0.z + p0.w + p1.x + p1.y + p1.z + p1.w
                      + p2.x + p2.y + p2.z + p2.w + p3.x + p3.y + p3.z + p3.w
                      + p4.x + p4.y + p4.z + p4.w + p5.x + p5.y + p5.z + p5.w
                      + p6.x + p6.y + p6.z + p6.w + p7.x + p7.y + p7.z + p7.w;
            sum += __shfl_xor_sync(0xffffffffu, sum, 1);
            const float corr = __expf(m_old - m_new);
            if (q == 0) {
                ms[row] = m_new;
                cs[row] = corr;
                ls[row] = ls[row] * corr + sum;
            }
            uint4 hi, lo;
            cvt8(p0, p1, hi, lo);
            uint32_t off = row * 128 + (((qU + 0) ^ (row & 7)) << 4);
            *(uint4*)(sm8 + A_PH + off) = hi;
            *(uint4*)(sm8 + A_PL + off) = lo;
            cvt8(p2, p3, hi, lo);
            off = row * 128 + (((qU + 1) ^ (row & 7)) << 4);
            *(uint4*)(sm8 + A_PH + off) = hi;
            *(uint4*)(sm8 + A_PL + off) = lo;
            cvt8(p4, p5, hi, lo);
            off = row * 128 + (((qU + 2) ^ (row & 7)) << 4);
            *(uint4*)(sm8 + A_PH + off) = hi;
            *(uint4*)(sm8 + A_PL + off) = lo;
            cvt8(p6, p7, hi, lo);
            off = row * 128 + (((qU + 3) ^ (row & 7)) << 4);
            *(uint4*)(sm8 + A_PH + off) = hi;
            *(uint4*)(sm8 + A_PL + off) = lo;
        }
        __syncthreads();

        // ---- rescale O and accumulate O += P @ V ----
        {
            O_RESC(oA0, oA1, 0)
            O_RESC(oB0, oB1, 1)
            O_RESC(oC0, oC1, 2)
            O_RESC(oD0, oD1, 3)
#pragma unroll 1
            for (int ks = 0; ks < 4; ks++) {
                const int vr = ks * 16 + v_rl;
                const uint32_t voff = vr * 128 + ((v_ch ^ (vr & 7)) << 4);
                U4 bH, bL;
                ldsm4t(bH, sb + A_VH + voff);
                ldsm4t(bL, sb + A_VL + voff);
                const uint32_t asw = (uint32_t)(((2 * ks + (lane >> 4)) ^ a_s7) << 4);
                U4 aH, aL;
                P_MT(oA0, oA1, a_r +  0)
                P_MT(oB0, oB1, a_r + 16)
                P_MT(oC0, oC1, a_r + 32)
                P_MT(oD0, oD1, a_r + 48)
            }
        }
    }

    // ---- epilogue ----
    {
        const int dcB = wn * 16 + 2 * (lane & 3);
        const int bb = bh >> 4;
        const int h  = bh & 15;
        float* obase = g_attn + ((size_t)(bb * T_ + qb * 128)) * D_ + h * DH_;
        O_WR(oA0, oA1, 0)
        O_WR(oB0, oB1, 1)
        O_WR(oC0, oC1, 2)
        O_WR(oD0, oD1, 3)
    }
}

// ---------------------------------------------------------------------------
extern "C" void kernel_launch(void* const* d_in, const int* in_sizes, int n_in,
                              void* d_out, int out_size)
{
    const float* x     = (const float*)d_in[0];
    const float* Wqkv  = (const float*)d_in[1];
    const float* bqkv  = (const float*)d_in[2];
    const float* Wproj = (const float*)d_in[3];
    const float* bproj = (const float*)d_in[4];
    float* out = (float*)d_out;

    cudaFuncSetAttribute((const void*)gemm_fused_kernel<1>,
                         cudaFuncAttributeMaxDynamicSharedMemorySize, GEMM_SMEM);
    cudaFuncSetAttribute((const void*)gemm_fused_kernel<0>,
                         cudaFuncAttributeMaxDynamicSharedMemorySize, GEMM_SMEM);
    cudaFuncSetAttribute((const void*)attn_mma_kernel,
                         cudaFuncAttributeMaxDynamicSharedMemorySize, ATTN_SMEM);

    // 1) QKV GEMM (proven R13) + head scatter
    gemm_fused_kernel<1><<<dim3(24, 128), 256, GEMM_SMEM>>>(x, Wqkv, bqkv, nullptr);

    // 2) RoPE
    RopeInv tab;
    for (int d = 0; d < 32; d++)
        tab.v[d] = (float)(1.0 / pow(10000.0, (double)((float)d / 32.0f)));
    rope_kernel<<<16384, 256>>>(tab);

    // 3) Flash attention (mma.sync, wide 128-query tiles)
    attn_mma_kernel<<<dim3(16, 64), 256, ATTN_SMEM>>>();

    // 4) Output projection (proven R13)
    gemm_fused_kernel<0><<<dim3(8, 128), 256, GEMM_SMEM>>>(nullptr, Wproj, bproj, out);
}